// round 10
// baseline (speedup 1.0000x reference)
#include <cuda_runtime.h>

#define T_TOTAL 34
#define H_OFF   4
#define TN      30     // output timesteps
#define AP      128    // agents per ego group
#define NEGO    32
#define NTHR    1024   // 8 octants x 128 agents
#define TPQ     4      // timesteps per octant (octant 7 handles 2)
#define STRD    (AP + 1)   // padded float stride -> conflict-free LDS

// d^2 prefilter: boxes <= 2.0 per side -> corner radius <= sqrt(8).
// Overlap (loss > 0) impossible if center dist > 2*sqrt(8); margin included.
#define D2_THRESH 33.0f

struct Smem {
    float         px[T_TOTAL][STRD];
    float         py[T_TOTAL][STRD];
    float         hd[T_TOTAL][STRD];
    unsigned char vmb[T_TOTAL][132];   // decoded valid mask; lane 0 = ego
    float         ecx[TN][4], ecy[TN][4];
    float4        epose[TN];           // (epx, epy, ce, se)
    float4        ebox;
    float4        abox[AP];
};

// max over 4 corners of min(long_t, lat_t) in frame at (px,py) rot (c,s).
__device__ __forceinline__ float corner_loss4(
    const float* cx, const float* cy, float px, float py,
    float c, float s, float bf, float br, float bl, float brt)
{
    float m = -1e30f;
    #pragma unroll
    for (int k = 0; k < 4; k++) {
        float dx = cx[k] - px, dy = cy[k] - py;
        float lx =  dx * c + dy * s;
        float ly = -dx * s + dy * c;
        float lt = fminf(fmaxf(bf  - lx, 0.0f), fmaxf(br  + lx, 0.0f));
        float la = fminf(fmaxf(bl  - ly, 0.0f), fmaxf(brt + ly, 0.0f));
        m = fmaxf(m, fminf(lt, la));
    }
    return m;
}

__global__ void __launch_bounds__(NTHR)
ttc_block(const float* __restrict__ posi,      // [N, 34, 2]
          const float* __restrict__ head,      // [N, 34]
          const float* __restrict__ box,       // [N, 4]  (f, r, l, rt)
          const void*  __restrict__ vm,        // [N, 34] bool (dtype detected)
          float* __restrict__ out)             // [32]
{
    extern __shared__ char smem_raw[];
    Smem* S = (Smem*)smem_raw;

    const int b    = blockIdx.x;       // ego group
    const int e    = b * AP;           // ego agent index (== lane 0 of group)
    const int tid  = threadIdx.x;
    const int lane = tid & (AP - 1);
    const int q    = tid >> 7;         // octant 0..7
    const int tbeg = q * TPQ;

    // ======== SINGLE MLP WINDOW: issue *all* loads, including both vm views ===
    // detect words (broadcast)
    const unsigned int* w = (const unsigned int*)vm;
    unsigned int dw[8];
    #pragma unroll
    for (int i = 0; i < 8; i++) dw[i] = w[i];

    // position slab: 2176 float4 coalesced
    const float4* pslab = (const float4*)(posi + (size_t)e * T_TOTAL * 2);
    float4 pv[3]; int pk[3]; int pcnt = 0;
    #pragma unroll
    for (int k = tid; k < AP * (T_TOTAL / 2); k += NTHR) { pv[pcnt] = pslab[k]; pk[pcnt] = k; pcnt++; }

    // heading slab: 1088 float4 coalesced
    const float4* hslab = (const float4*)(head + (size_t)e * T_TOTAL);
    float4 hv[2]; int hk[2]; int hcnt = 0;
    #pragma unroll
    for (int k = tid; k < AP * T_TOTAL / 4; k += NTHR) { hv[hcnt] = hslab[k]; hk[hcnt] = k; hcnt++; }

    // box slab
    float4 bv; const bool has_b = (tid < AP);
    if (has_b) bv = *(const float4*)(box + (size_t)(e + tid) * 4);

    // vm slab, WORD interpretation (speculative): 1088 uint4
    const uint4* vw = (const uint4*)((const unsigned int*)vm + (size_t)e * T_TOTAL);
    uint4 vmw[2]; int vmwk[2]; int vmwcnt = 0;
    #pragma unroll
    for (int k = tid; k < AP * T_TOTAL / 4; k += NTHR) { vmw[vmwcnt] = vw[k]; vmwk[vmwcnt] = k; vmwcnt++; }

    // vm slab, BYTE interpretation (speculative): 272 uint4
    const uint4* vb = (const uint4*)((const unsigned char*)vm + (size_t)e * T_TOTAL);
    uint4 vmb_v; int vmb_k = -1;
    if (tid < AP * T_TOTAL / 16) { vmb_v = vb[tid]; vmb_k = tid; }

    // ego pose inputs (threads 0..29; broadcast-friendly lines)
    float2 ep0, ep1; float eyaw; float4 eb_ego;
    if (tid < TN) {
        const int ti  = tid + H_OFF;
        const int ebp = (e * T_TOTAL + ti) * 2;
        ep0 = *(const float2*)(posi + ebp - 2);
        ep1 = *(const float2*)(posi + ebp);
        eyaw = head[e * T_TOTAL + ti];
        eb_ego = *(const float4*)(box + (size_t)e * 4);
    }

    // ======== detection: pure ALU, selects which vm registers to decode ======
    bool wordmode = true;              // int32/float32 bool: entry = (word != 0)
    #pragma unroll
    for (int i = 0; i < 8; i++)
        wordmode = wordmode && (dw[i] <= 1u || dw[i] == 0x3F800000u);

    // ======== stage everything -> smem =======================================
    #pragma unroll
    for (int j = 0; j < 3; j++) if (j < pcnt) {
        int k  = pk[j];
        int a  = k / (T_TOTAL / 2);
        int t0 = 2 * (k - a * (T_TOTAL / 2));
        S->px[t0][a]     = pv[j].x;  S->py[t0][a]     = pv[j].y;
        S->px[t0 + 1][a] = pv[j].z;  S->py[t0 + 1][a] = pv[j].w;
    }
    #pragma unroll
    for (int j = 0; j < 2; j++) if (j < hcnt) {
        int idx = 4 * hk[j];
        int a = idx / T_TOTAL, tt = idx - a * T_TOTAL;
        float vv[4] = { hv[j].x, hv[j].y, hv[j].z, hv[j].w };
        #pragma unroll
        for (int u = 0; u < 4; u++) {
            S->hd[tt][a] = vv[u];
            if (++tt == T_TOTAL) { tt = 0; ++a; }
        }
    }
    if (has_b) S->abox[tid] = bv;

    if (wordmode) {                    // uniform branch
        #pragma unroll
        for (int j = 0; j < 2; j++) if (j < vmwcnt) {
            int idx = 4 * vmwk[j];
            int a = idx / T_TOTAL, tt = idx - a * T_TOTAL;
            unsigned int uu[4] = { vmw[j].x, vmw[j].y, vmw[j].z, vmw[j].w };
            #pragma unroll
            for (int u = 0; u < 4; u++) {
                S->vmb[tt][a] = (uu[u] != 0u);
                if (++tt == T_TOTAL) { tt = 0; ++a; }
            }
        }
    } else {
        if (vmb_k >= 0) {
            int idx = 16 * vmb_k;
            int a = idx / T_TOTAL, tt = idx - a * T_TOTAL;
            unsigned int uu[4] = { vmb_v.x, vmb_v.y, vmb_v.z, vmb_v.w };
            #pragma unroll
            for (int wj = 0; wj < 4; wj++)
                #pragma unroll
                for (int bj = 0; bj < 4; bj++) {
                    S->vmb[tt][a] = ((uu[wj] >> (8 * bj)) & 0xFFu) != 0u;
                    if (++tt == T_TOTAL) { tt = 0; ++a; }
                }
        }
    }

    if (tid < TN) {
        float epx = fmaf(ep1.x - ep0.x, 1.9f, ep1.x);
        float epy = fmaf(ep1.y - ep0.y, 1.9f, ep1.y);
        float ce = cosf(eyaw), se = sinf(eyaw);
        const float lxs[4] = { eb_ego.x,  eb_ego.x, -eb_ego.y, -eb_ego.y };
        const float lys[4] = { eb_ego.z, -eb_ego.w, -eb_ego.w,  eb_ego.z };
        #pragma unroll
        for (int k = 0; k < 4; k++) {
            S->ecx[tid][k] = lxs[k] * ce - lys[k] * se + epx;
            S->ecy[tid][k] = lxs[k] * se + lys[k] * ce + epy;
        }
        S->epose[tid] = make_float4(epx, epy, ce, se);
        if (tid == 0) S->ebox = eb_ego;
    }
    __syncthreads();   // single barrier: everything staged

    // ======== compute (pure SMEM/ALU, vm gate inline) =========================
    bool viol = false;
    if (lane != 0) {                   // lane 0 is the ego itself (excluded edge)
        #pragma unroll
        for (int i = 0; i < TPQ; i++) {
            const int t = tbeg + i;
            if (t >= TN) break;        // uniform (octant 7 only)
            const int ti = t + H_OFF;

            float p0x = S->px[ti - 1][lane], p0y = S->py[ti - 1][lane];
            float p1x = S->px[ti][lane],     p1y = S->py[ti][lane];
            float apx = fmaf(p1x - p0x, 1.9f, p1x);
            float apy = fmaf(p1y - p0y, 1.9f, p1y);

            float4 ep = S->epose[t];
            float ddx = apx - ep.x, ddy = apy - ep.y;
            float d2 = fmaf(ddx, ddx, ddy * ddy);
            bool ok = (d2 <= D2_THRESH) && S->vmb[ti][lane] && S->vmb[ti][0];
            if (!ok) continue;         // ~99% reject

            float ayaw = S->hd[ti][lane];
            float4 ab  = S->abox[lane];
            float ca = cosf(ayaw), sa = sinf(ayaw);

            float ecx[4], ecy[4];
            #pragma unroll
            for (int k = 0; k < 4; k++) { ecx[k] = S->ecx[t][k]; ecy[k] = S->ecy[t][k]; }
            float L1 = corner_loss4(ecx, ecy, apx, apy, ca, sa,
                                    ab.x, ab.y, ab.z, ab.w);

            float acx[4], acy[4];
            const float lxs[4] = { ab.x,  ab.x, -ab.y, -ab.y };
            const float lys[4] = { ab.z, -ab.w, -ab.w,  ab.z };
            #pragma unroll
            for (int k = 0; k < 4; k++) {
                acx[k] = lxs[k] * ca - lys[k] * sa + apx;
                acy[k] = lxs[k] * sa + lys[k] * ca + apy;
            }
            float4 eb = S->ebox;
            float L2 = corner_loss4(acx, acy, ep.x, ep.y, ep.z, ep.w,
                                    eb.x, eb.y, eb.z, eb.w);

            viol = viol || (fmaxf(L1, L2) > 0.0f);
        }
    }

    int any = __syncthreads_or(viol ? 1 : 0);
    if (tid == 0) out[b] = any ? 0.0f : 1.0f;
}

extern "C" void kernel_launch(void* const* d_in, const int* in_sizes, int n_in,
                              void* d_out, int out_size) {
    const float* posi = (const float*)d_in[0];   // infer_position
    const float* head = (const float*)d_in[1];   // infer_heading
    const float* box  = (const float*)d_in[2];   // box
    const void*  vm   = (const void*)d_in[3];    // infer_valid_mask
    float* out = (float*)d_out;

    static bool attr_set = false;
    if (!attr_set) {
        cudaFuncSetAttribute(ttc_block, cudaFuncAttributeMaxDynamicSharedMemorySize,
                             (int)sizeof(Smem));
        attr_set = true;
    }
    ttc_block<<<NEGO, NTHR, sizeof(Smem)>>>(posi, head, box, vm, out);
}

// round 11
// speedup vs baseline: 1.3349x; 1.3349x over previous
#include <cuda_runtime.h>

#define T_TOTAL 34
#define H_OFF   4
#define TN      30     // output timesteps
#define AP      128    // agents per ego group
#define NEGO    32
#define NTHR    1024   // 8 octants x 128 agents
#define TPQ     4      // timesteps per octant (octant 7 handles 2)

// d^2 prefilter: boxes <= 2.0 per side -> corner radius <= sqrt(8).
// Overlap (loss > 0) impossible if center dist > 2*sqrt(8); margin included.
#define D2_THRESH 33.0f

#define NPOS4 (AP * T_TOTAL / 2)   // 2176 float4 in position slab
#define NHD4  (AP * T_TOTAL / 4)   // 1088 float4 in heading slab
#define NVMW4 (AP * T_TOTAL / 4)   // 1088 uint4  in vm slab (word layout)
#define NVMB4 (AP * T_TOTAL / 16)  //  272 uint4  in vm slab (byte layout)

struct Smem {
    float2 pxy[T_TOTAL][AP + 2];       // transposed positions, padded stride
    float4 hdlin[NHD4];                // raw linear headings [a*34 + t]
    uint4  vmraw[NVMW4];               // raw vm slab (words or bytes at front)
    float  ecx[TN][4], ecy[TN][4];
    float4 epose[TN];                  // (epx, epy, ce, se)
    float4 ebox;
    float4 abox[AP];
};

// max over 4 corners of min(long_t, lat_t) in frame at (px,py) rot (c,s).
__device__ __forceinline__ float corner_loss4(
    const float* cx, const float* cy, float px, float py,
    float c, float s, float bf, float br, float bl, float brt)
{
    float m = -1e30f;
    #pragma unroll
    for (int k = 0; k < 4; k++) {
        float dx = cx[k] - px, dy = cy[k] - py;
        float lx =  dx * c + dy * s;
        float ly = -dx * s + dy * c;
        float lt = fminf(fmaxf(bf  - lx, 0.0f), fmaxf(br  + lx, 0.0f));
        float la = fminf(fmaxf(bl  - ly, 0.0f), fmaxf(brt + ly, 0.0f));
        m = fmaxf(m, fminf(lt, la));
    }
    return m;
}

__global__ void __launch_bounds__(NTHR)
ttc_block(const float* __restrict__ posi,      // [N, 34, 2]
          const float* __restrict__ head,      // [N, 34]
          const float* __restrict__ box,       // [N, 4]  (f, r, l, rt)
          const void*  __restrict__ vm,        // [N, 34] bool (dtype detected)
          float* __restrict__ out)             // [32]
{
    extern __shared__ char smem_raw[];
    Smem* S = (Smem*)smem_raw;

    const int b    = blockIdx.x;       // ego group
    const int e    = b * AP;           // ego agent index (== lane 0 of group)
    const int tid  = threadIdx.x;
    const int lane = tid & (AP - 1);
    const int q    = tid >> 7;         // octant 0..7
    const int tbeg = q * TPQ;

    // ======== SINGLE MLP WINDOW: issue all loads (incl. both vm views) ========
    const unsigned int* w = (const unsigned int*)vm;
    unsigned int dw[8];
    #pragma unroll
    for (int i = 0; i < 8; i++) dw[i] = w[i];

    const float4* pslab = (const float4*)(posi + (size_t)e * T_TOTAL * 2);
    float4 pv0, pv1, pv2;
    pv0 = pslab[tid];
    pv1 = pslab[tid + NTHR];
    const bool has_p2 = (tid + 2 * NTHR < NPOS4);
    if (has_p2) pv2 = pslab[tid + 2 * NTHR];

    const float4* hslab = (const float4*)(head + (size_t)e * T_TOTAL);
    float4 hv0, hv1;
    const bool has_h0 = (tid < NHD4);
    const bool has_h1 = (tid + NTHR < NHD4);   // tid < 64
    if (has_h0) hv0 = hslab[tid];
    if (has_h1) hv1 = hslab[tid + NTHR];

    float4 bv; const bool has_b = (tid < AP);
    if (has_b) bv = *(const float4*)(box + (size_t)(e + tid) * 4);

    // vm word view (speculative)
    const uint4* vw = (const uint4*)((const unsigned int*)vm + (size_t)e * T_TOTAL);
    uint4 vw0, vw1;
    if (has_h0) vw0 = vw[tid];
    if (has_h1) vw1 = vw[tid + NTHR];
    // vm byte view (speculative)
    const uint4* vb = (const uint4*)((const unsigned char*)vm + (size_t)e * T_TOTAL);
    uint4 vb0; const bool has_vb = (tid < NVMB4);
    if (has_vb) vb0 = vb[tid];

    // ego pose inputs (threads 0..29)
    float2 ep0, ep1; float eyaw; float4 eb_ego;
    if (tid < TN) {
        const int ti  = tid + H_OFF;
        const int ebp = (e * T_TOTAL + ti) * 2;
        ep0 = *(const float2*)(posi + ebp - 2);
        ep1 = *(const float2*)(posi + ebp);
        eyaw = head[e * T_TOTAL + ti];
        eb_ego = *(const float4*)(box + (size_t)e * 4);
    }

    // ======== detection (pure ALU) ===========================================
    bool wordmode = true;              // int32/float32 bool: entry = (word != 0)
    #pragma unroll
    for (int i = 0; i < 8; i++)
        wordmode = wordmode && (dw[i] <= 1u || dw[i] == 0x3F800000u);

    // ======== stage (straight-line, minimal index math) ======================
    {   // positions: transpose via /17 decode, 2x STS.64 per float4
        int k = tid, a = k / 17, t0 = 2 * (k - a * 17);
        S->pxy[t0][a]     = make_float2(pv0.x, pv0.y);
        S->pxy[t0 + 1][a] = make_float2(pv0.z, pv0.w);
        k = tid + NTHR; a = k / 17; t0 = 2 * (k - a * 17);
        S->pxy[t0][a]     = make_float2(pv1.x, pv1.y);
        S->pxy[t0 + 1][a] = make_float2(pv1.z, pv1.w);
        if (has_p2) {
            k = tid + 2 * NTHR; a = k / 17; t0 = 2 * (k - a * 17);
            S->pxy[t0][a]     = make_float2(pv2.x, pv2.y);
            S->pxy[t0 + 1][a] = make_float2(pv2.z, pv2.w);
        }
    }
    if (has_h0) S->hdlin[tid] = hv0;               // raw linear
    if (has_h1) S->hdlin[tid + NTHR] = hv1;
    if (wordmode) {                                // uniform branch
        if (has_h0) S->vmraw[tid] = vw0;
        if (has_h1) S->vmraw[tid + NTHR] = vw1;
    } else {
        if (has_vb) S->vmraw[tid] = vb0;
    }
    if (has_b) S->abox[tid] = bv;

    if (tid < TN) {
        float epx = fmaf(ep1.x - ep0.x, 1.9f, ep1.x);
        float epy = fmaf(ep1.y - ep0.y, 1.9f, ep1.y);
        float ce = cosf(eyaw), se = sinf(eyaw);
        const float lxs[4] = { eb_ego.x,  eb_ego.x, -eb_ego.y, -eb_ego.y };
        const float lys[4] = { eb_ego.z, -eb_ego.w, -eb_ego.w,  eb_ego.z };
        #pragma unroll
        for (int k = 0; k < 4; k++) {
            S->ecx[tid][k] = lxs[k] * ce - lys[k] * se + epx;
            S->ecy[tid][k] = lxs[k] * se + lys[k] * ce + epy;
        }
        S->epose[tid] = make_float4(epx, epy, ce, se);
        if (tid == 0) S->ebox = eb_ego;
    }
    __syncthreads();   // single barrier

    // ======== compute (pure SMEM/ALU; lazy decode for survivors) =============
    const unsigned int*  vmw_s = (const unsigned int*)S->vmraw;
    const unsigned char* vmb_s = (const unsigned char*)S->vmraw;
    const float*         hd_s  = (const float*)S->hdlin;

    bool viol = false;
    if (lane != 0) {                   // lane 0 is the ego itself (excluded edge)
        #pragma unroll
        for (int i = 0; i < TPQ; i++) {
            const int t = tbeg + i;
            if (t >= TN) break;        // uniform (octant 7 only)
            const int ti = t + H_OFF;

            float2 p0 = S->pxy[ti - 1][lane];
            float2 p1 = S->pxy[ti][lane];
            float apx = fmaf(p1.x - p0.x, 1.9f, p1.x);
            float apy = fmaf(p1.y - p0.y, 1.9f, p1.y);

            float4 ep = S->epose[t];
            float ddx = apx - ep.x, ddy = apy - ep.y;
            if (fmaf(ddx, ddx, ddy * ddy) > D2_THRESH) continue;  // ~99% reject

            // valid-mask gate (rare, lazy decode from raw slab)
            bool valid;
            if (wordmode) valid = (vmw_s[lane * T_TOTAL + ti] != 0u) &&
                                  (vmw_s[ti] != 0u);
            else          valid = (vmb_s[lane * T_TOTAL + ti] != 0) &&
                                  (vmb_s[ti] != 0);
            if (!valid) continue;

            float ayaw = hd_s[lane * T_TOTAL + ti];
            float4 ab  = S->abox[lane];
            float ca = cosf(ayaw), sa = sinf(ayaw);

            float ecx[4], ecy[4];
            #pragma unroll
            for (int k = 0; k < 4; k++) { ecx[k] = S->ecx[t][k]; ecy[k] = S->ecy[t][k]; }
            float L1 = corner_loss4(ecx, ecy, apx, apy, ca, sa,
                                    ab.x, ab.y, ab.z, ab.w);

            float acx[4], acy[4];
            const float lxs[4] = { ab.x,  ab.x, -ab.y, -ab.y };
            const float lys[4] = { ab.z, -ab.w, -ab.w,  ab.z };
            #pragma unroll
            for (int k = 0; k < 4; k++) {
                acx[k] = lxs[k] * ca - lys[k] * sa + apx;
                acy[k] = lxs[k] * sa + lys[k] * ca + apy;
            }
            float4 eb = S->ebox;
            float L2 = corner_loss4(acx, acy, ep.x, ep.y, ep.z, ep.w,
                                    eb.x, eb.y, eb.z, eb.w);

            viol = viol || (fmaxf(L1, L2) > 0.0f);
        }
    }

    int any = __syncthreads_or(viol ? 1 : 0);
    if (tid == 0) out[b] = any ? 0.0f : 1.0f;
}

extern "C" void kernel_launch(void* const* d_in, const int* in_sizes, int n_in,
                              void* d_out, int out_size) {
    const float* posi = (const float*)d_in[0];   // infer_position
    const float* head = (const float*)d_in[1];   // infer_heading
    const float* box  = (const float*)d_in[2];   // box
    const void*  vm   = (const void*)d_in[3];    // infer_valid_mask
    float* out = (float*)d_out;

    static bool attr_set = false;
    if (!attr_set) {
        cudaFuncSetAttribute(ttc_block, cudaFuncAttributeMaxDynamicSharedMemorySize,
                             (int)sizeof(Smem));
        attr_set = true;
    }
    ttc_block<<<NEGO, NTHR, sizeof(Smem)>>>(posi, head, box, vm, out);
}